// round 16
// baseline (speedup 1.0000x reference)
#include <cuda_runtime.h>
#include <cuda_bf16.h>
#include <cuda_fp16.h>
#include <cstdint>

// ============================================================================
// Problem constants
// ============================================================================
#define T_TOK   8192        // B*S
#define D_IN    4096
#define D_OUT   4096
#define N_EXP   8
#define RANK    16
#define KEXTRA  128         // E*R
#define KSTR    4224        // D_IN + KEXTRA (extended K)
#define SCALING 2.0f

// ============================================================================
// Persistent device scratch (static arrays: allocation-free)
// ============================================================================
__device__ __half g_x16[(size_t)T_TOK * KSTR];    // 69.2 MB
__device__ __half g_W16[(size_t)D_OUT * KSTR];    // 34.6 MB
__device__ __half g_A16[(size_t)KEXTRA * D_IN];   // 1 MB
__device__ float  g_hp[2][(size_t)T_TOK * KEXTRA]; // split-K partials, 8 MB
__device__ float  g_rw[(size_t)T_TOK * N_EXP];
__device__ float  g_dummy_rw[2 * T_TOK * N_EXP];

// ============================================================================
// Helpers (sm_80-compatible PTX only; ptxas targets plain sm_103)
// ============================================================================
__device__ __forceinline__ uint32_t smem_to_u32(const void* p) {
    uint32_t a;
    asm("{ .reg .u64 t; cvta.to.shared.u64 t, %1; cvt.u32.u64 %0, t; }" : "=r"(a) : "l"(p));
    return a;
}
__device__ __forceinline__ void cpasync16(uint32_t saddr, const void* g) {
    asm volatile("cp.async.cg.shared.global [%0], [%1], 16;" :: "r"(saddr), "l"(g));
}
__device__ __forceinline__ void cp_commit() {
    asm volatile("cp.async.commit_group;" ::: "memory");
}
__device__ __forceinline__ void ldsm4(uint32_t* r, uint32_t addr) {
    asm volatile("ldmatrix.sync.aligned.m8n8.x4.shared.b16 {%0,%1,%2,%3}, [%4];"
                 : "=r"(r[0]), "=r"(r[1]), "=r"(r[2]), "=r"(r[3]) : "r"(addr));
}
__device__ __forceinline__ void mma16816(float* c, const uint32_t* a, const uint32_t* b) {
    asm volatile(
        "mma.sync.aligned.m16n8k16.row.col.f32.f16.f16.f32 "
        "{%0,%1,%2,%3}, {%4,%5,%6,%7}, {%8,%9}, {%0,%1,%2,%3};"
        : "+f"(c[0]), "+f"(c[1]), "+f"(c[2]), "+f"(c[3])
        : "r"(a[0]), "r"(a[1]), "r"(a[2]), "r"(a[3]), "r"(b[0]), "r"(b[1]));
}

// ============================================================================
// Kernel: prep — heterogeneous grid.
//   blocks [0,128):        gate (fp32) + fused x->fp16 (identical math to R15)
//   blocks [128, 128+16384): W->fp16
//   blocks [+512):          lora_A->fp16
//   blocks [+2048):         lora_B pack
// ============================================================================
#define GT_XROW 68
#define GT_XBUF (64 * GT_XROW)
#define GT_WBUF (8 * GT_XROW)
#define GT_XB0  0
#define GT_WS0  (2 * GT_XBUF)
#define GT_GS0  (GT_WS0 + 2 * GT_WBUF)
#define GT_FLOATS (GT_GS0 + 64 * 9)
#define GT_SMEM (GT_FLOATS * 4)            // 41472

#define PREP_GATE_BLKS 128
#define PREP_W_BLKS    16384
#define PREP_A_BLKS    512
#define PREP_L_BLKS    2048
#define PREP_GRID (PREP_GATE_BLKS + PREP_W_BLKS + PREP_A_BLKS + PREP_L_BLKS)

__device__ __forceinline__ void gate_issue(uint32_t sb, int s, int kb,
                                           int tok0, int tid,
                                           const float* __restrict__ x,
                                           const float* __restrict__ routeW) {
#pragma unroll
    for (int t = 0; t < 4; ++t) {          // x chunk: 64 rows x 64 floats
        int idx = tid + 256 * t;
        int row = idx >> 4, c16 = idx & 15;
        uint32_t so = sb + (uint32_t)((GT_XB0 + s * GT_XBUF + row * GT_XROW + c16 * 4) * 4);
        cpasync16(so, x + (size_t)(tok0 + row) * D_IN + kb * 64 + c16 * 4);
    }
    if (tid < 128) {                       // routeW chunk: 8 rows x 64 floats
        int row = tid >> 4, c16 = tid & 15;
        uint32_t so = sb + (uint32_t)((GT_WS0 + s * GT_WBUF + row * GT_XROW + c16 * 4) * 4);
        cpasync16(so, routeW + (size_t)row * D_IN + kb * 64 + c16 * 4);
    }
    cp_commit();
}

__device__ __forceinline__ void conv_store(const float* src, __half* dst,
                                           size_t ridx, int c4,
                                           int src_stride, int dst_stride) {
    float4 v = *(const float4*)(src + ridx * src_stride + c4 * 4);
    __half2 h0 = __floats2half2_rn(v.x, v.y);
    __half2 h1 = __floats2half2_rn(v.z, v.w);
    uint2 o;
    o.x = *(uint32_t*)&h0;
    o.y = *(uint32_t*)&h1;
    *(uint2*)(dst + ridx * dst_stride + c4 * 4) = o;
}

__global__ void __launch_bounds__(256) prep_kernel(
    const float* __restrict__ x, const float* __restrict__ routeW,
    const float* __restrict__ W, const float* __restrict__ loraA,
    const float* __restrict__ loraB,
    float* __restrict__ out_rw, float* __restrict__ out_gs)
{
    extern __shared__ float sm[];
    const int b = blockIdx.x;
    const int tid = threadIdx.x;

    if (b >= PREP_GATE_BLKS) {
        int cb = b - PREP_GATE_BLKS;
        if (cb < PREP_W_BLKS) {
            size_t idx = (size_t)cb * 256 + tid;               // D_OUT*1024
            conv_store(W, g_W16, idx >> 10, (int)(idx & 1023), D_IN, KSTR);
        } else if (cb < PREP_W_BLKS + PREP_A_BLKS) {
            size_t idx = (size_t)(cb - PREP_W_BLKS) * 256 + tid;   // KEXTRA*1024
            conv_store(loraA, g_A16, idx >> 10, (int)(idx & 1023), D_IN, D_IN);
        } else {
            int idx = (cb - PREP_W_BLKS - PREP_A_BLKS) * 256 + tid; // D_OUT*KEXTRA
            int o = idx >> 7, kk = idx & 127;
            int e = kk >> 4, r = kk & 15;
            g_W16[(size_t)o * KSTR + D_IN + kk] =
                __float2half_rn(loraB[((size_t)e * D_OUT + o) * RANK + r]);
        }
        return;
    }

    // ---- gate part (identical math to R15 gate_kernel) ----
    const uint32_t sb = smem_to_u32(sm);
    float* gs = sm + GT_GS0;
    const int tok0 = b * 64;
    const int t  = tid >> 2;
    const int eq = tid & 3;

    gate_issue(sb, 0, 0, tok0, tid, x, routeW);
    gate_issue(sb, 1, 1, tok0, tid, x, routeW);

    float a0 = 0.0f, a1 = 0.0f;
#pragma unroll 1
    for (int kb = 0; kb < D_IN / 64; ++kb) {
        const int s = kb & 1;
        if (kb < D_IN / 64 - 1) asm volatile("cp.async.wait_group 1;" ::: "memory");
        else                    asm volatile("cp.async.wait_group 0;" ::: "memory");
        __syncthreads();

        const float* xb = sm + GT_XB0 + s * GT_XBUF + t * GT_XROW;
        const float* w0 = sm + GT_WS0 + s * GT_WBUF + eq * GT_XROW;
        const float* w1 = w0 + 4 * GT_XROW;
#pragma unroll
        for (int k4 = 0; k4 < 16; ++k4) {
            float4 xv = *(const float4*)(xb + k4 * 4);
            float4 wa = *(const float4*)(w0 + k4 * 4);
            float4 wb = *(const float4*)(w1 + k4 * 4);
            a0 = fmaf(xv.x, wa.x, a0); a0 = fmaf(xv.y, wa.y, a0);
            a0 = fmaf(xv.z, wa.z, a0); a0 = fmaf(xv.w, wa.w, a0);
            a1 = fmaf(xv.x, wb.x, a1); a1 = fmaf(xv.y, wb.y, a1);
            a1 = fmaf(xv.z, wb.z, a1); a1 = fmaf(xv.w, wb.w, a1);
        }
        {
            const float* xr = sm + GT_XB0 + s * GT_XBUF + t * GT_XROW + eq * 16;
            __half* dst = g_x16 + (size_t)(tok0 + t) * KSTR + kb * 64 + eq * 16;
#pragma unroll
            for (int j = 0; j < 4; ++j) {
                float4 v = *(const float4*)(xr + j * 4);
                __half2 p0 = __floats2half2_rn(v.x, v.y);
                __half2 p1 = __floats2half2_rn(v.z, v.w);
                uint2 o;
                o.x = *(uint32_t*)&p0;
                o.y = *(uint32_t*)&p1;
                *(uint2*)(dst + j * 4) = o;
            }
        }
        __syncthreads();
        if (kb + 2 < D_IN / 64) gate_issue(sb, s, kb + 2, tok0, tid, x, routeW);
    }

    gs[t * 9 + eq] = a0;
    gs[t * 9 + eq + 4] = a1;
    __syncthreads();

    if (tid < 64) {
        float g[N_EXP], m = -1e30f;
#pragma unroll
        for (int j = 0; j < N_EXP; ++j) { g[j] = gs[tid * 9 + j]; m = fmaxf(m, g[j]); }
        float p[N_EXP], s = 0.0f;
#pragma unroll
        for (int j = 0; j < N_EXP; ++j) { p[j] = expf(g[j] - m); s += p[j]; }
        float inv = 1.0f / s;
#pragma unroll
        for (int j = 0; j < N_EXP; ++j) p[j] *= inv;

        int i1 = 0;
#pragma unroll
        for (int j = 1; j < N_EXP; ++j) if (p[j] > p[i1]) i1 = j;
        int i2 = (i1 == 0) ? 1 : 0;
#pragma unroll
        for (int j = 0; j < N_EXP; ++j) if (j != i1 && p[j] > p[i2]) i2 = j;

        float denom = p[i1] + p[i2] + 1e-9f;
        float w1 = p[i1] / denom, w2 = p[i2] / denom;

        size_t ob = (size_t)(tok0 + tid) * N_EXP;
#pragma unroll
        for (int j = 0; j < N_EXP; ++j) {
            out_gs[ob + j] = g[j];
            float w = (j == i1) ? w1 : ((j == i2) ? w2 : 0.0f);
            out_rw[ob + j] = w;
            g_rw[ob + j] = w;
        }
    }
}

// ============================================================================
// Kernel: hgemm — h = x * lora_A^T, SPLIT-K x2 (grid 128 m-tiles x 2 k-halves,
// 256 CTAs -> all SMs busy). fp32 partials to g_hp[ks]. Tile 64x128, 8 warps,
// 4-stage cp.async, 32 chunks per CTA.
// ============================================================================
#define H_PA 8192
#define H_PB 16384
#define H_STG (H_PA + H_PB)            // 24576
#define H_SMEM (4 * H_STG)             // 98304
#define H_CHUNKS 32                    // per k-half

__device__ __forceinline__ void h_issue(uint32_t sb, int s, int c, int m0, int tid) {
    uint32_t sbase = sb + s * H_STG;
    size_t koff = (size_t)c * 64;
#pragma unroll
    for (int t = 0; t < 2; ++t) {                       // A: 64 rows * 8
        int idx = tid + 256 * t;
        int row = idx >> 3, c8 = idx & 7;
        uint32_t so = (uint32_t)(row * 128 + ((c8 * 16) ^ ((row & 7) << 4)));
        cpasync16(sbase + so, g_x16 + (size_t)(m0 + row) * KSTR + koff + c8 * 8);
    }
#pragma unroll
    for (int t = 0; t < 4; ++t) {                       // B: 128 rows * 8
        int idx = tid + 256 * t;
        int row = idx >> 3, c8 = idx & 7;
        uint32_t so = (uint32_t)(row * 128 + ((c8 * 16) ^ ((row & 7) << 4)));
        cpasync16(sbase + H_PA + so, g_A16 + (size_t)row * D_IN + koff + c8 * 8);
    }
    cp_commit();
}

__global__ void __launch_bounds__(256, 1) hgemm_kernel() {
    extern __shared__ char smc[];
    const uint32_t sb = smem_to_u32(smc);
    const int tid = threadIdx.x;
    const int lane = tid & 31;
    const int wid = tid >> 5;
    const int wm = wid >> 2;        // 0..1
    const int wn = wid & 3;         // 0..3
    const int m0 = blockIdx.x * 64;
    const int ks = blockIdx.y;      // 0..1 k-half
    const int cbase = ks * H_CHUNKS;

    const int jg = lane >> 3, rr = lane & 7;
    const uint32_t xorv = (uint32_t)(rr << 4);
    const uint32_t arow = (uint32_t)((jg & 1) * 8 + rr);
    const uint32_t akb  = (uint32_t)((jg >> 1) * 16);
    const uint32_t brow = (uint32_t)((jg >> 1) * 8 + rr);
    const uint32_t bkb  = (uint32_t)((jg & 1) * 16);

    float acc[2][4][4];
#pragma unroll
    for (int i = 0; i < 2; ++i)
#pragma unroll
        for (int j = 0; j < 4; ++j)
#pragma unroll
            for (int q = 0; q < 4; ++q) acc[i][j][q] = 0.0f;

    h_issue(sb, 0, cbase + 0, m0, tid);
    h_issue(sb, 1, cbase + 1, m0, tid);
    h_issue(sb, 2, cbase + 2, m0, tid);

#pragma unroll 1
    for (int c = 0; c < H_CHUNKS; ++c) {
        const int s = c & 3;
        if (c < H_CHUNKS - 2)       asm volatile("cp.async.wait_group 2;" ::: "memory");
        else if (c == H_CHUNKS - 2) asm volatile("cp.async.wait_group 1;" ::: "memory");
        else                        asm volatile("cp.async.wait_group 0;" ::: "memory");
        __syncthreads();
        if (c + 3 < H_CHUNKS) h_issue(sb, (c + 3) & 3, cbase + c + 3, m0, tid);

        const uint32_t sA = sb + s * H_STG;
        const uint32_t sB = sA + H_PA;
#pragma unroll
        for (int k16 = 0; k16 < 4; ++k16) {
            const uint32_t kA = ((uint32_t)(k16 * 32) + akb) ^ xorv;
            const uint32_t kB = ((uint32_t)(k16 * 32) + bkb) ^ xorv;
            uint32_t ah[2][4];
#pragma unroll
            for (int i = 0; i < 2; ++i) {
                uint32_t ro = (uint32_t)((wm * 32 + i * 16 + arow) * 128);
                ldsm4(ah[i], sA + ro + kA);
            }
#pragma unroll
            for (int j2 = 0; j2 < 2; ++j2) {
                uint32_t bh[4];
                uint32_t ro = (uint32_t)((wn * 32 + j2 * 16 + brow) * 128);
                ldsm4(bh, sB + ro + kB);
#pragma unroll
                for (int i = 0; i < 2; ++i) {
                    mma16816(acc[i][j2 * 2],     ah[i], bh);
                    mma16816(acc[i][j2 * 2 + 1], ah[i], bh + 2);
                }
            }
        }
    }

    // Epilogue: store fp32 partials
    float* hp = g_hp[ks];
    const int gi = lane >> 2;
    const int tg = lane & 3;
#pragma unroll
    for (int i = 0; i < 2; ++i)
#pragma unroll
        for (int j = 0; j < 4; ++j) {
            int col = wn * 32 + j * 8 + tg * 2;
#pragma unroll
            for (int half = 0; half < 2; ++half) {
                int r = m0 + wm * 32 + i * 16 + gi + half * 8;
                float2 v = make_float2(acc[i][j][half * 2 + 0], acc[i][j][half * 2 + 1]);
                *(float2*)(hp + (size_t)r * KEXTRA + col) = v;
            }
        }
}

// ============================================================================
// Kernel: combine — g = SCALING * rw * (hp0 + hp1) -> fp16 lora cols of g_x16
// ============================================================================
__global__ void __launch_bounds__(256) combine_kernel() {
    int idx = blockIdx.x * 256 + threadIdx.x;   // T_TOK*32 threads, 4 cols each
    int t = idx >> 5;
    int c = (idx & 31) * 4;
    float rw = SCALING * g_rw[(size_t)t * N_EXP + (c >> 4)];
    const float* p0 = g_hp[0] + (size_t)t * KEXTRA + c;
    const float* p1 = g_hp[1] + (size_t)t * KEXTRA + c;
    float4 a = *(const float4*)p0;
    float4 b = *(const float4*)p1;
    __half2 h0 = __floats2half2_rn((a.x + b.x) * rw, (a.y + b.y) * rw);
    __half2 h1 = __floats2half2_rn((a.z + b.z) * rw, (a.w + b.w) * rw);
    uint2 o;
    o.x = *(uint32_t*)&h0;
    o.y = *(uint32_t*)&h1;
    *(uint2*)(g_x16 + (size_t)t * KSTR + D_IN + c) = o;
}

// ============================================================================
// Kernel: main GEMM — out = bias + Xext * Wext^T over extended K (lora fused).
// FROZEN at measured plateau: 128x128xKC64, 4 warps (2x2) of 64x64 tiles,
// 128 threads, occ 2, 3-stage (tensor ~75% = HMMA-fallback ceiling).
// ============================================================================
#define G_PA 16384
#define G_PB 16384
#define G_STG (G_PA + G_PB)            // 32768
#define G_SMEM (3 * G_STG)             // 98304
#define G_NCH (KSTR / 64)              // 66

__device__ __forceinline__ void m_issue(uint32_t sb, int s, int c, int m0, int n0, int tid) {
    uint32_t sbase = sb + s * G_STG;
    size_t koff = (size_t)c * 64;
#pragma unroll
    for (int t = 0; t < 8; ++t) {                       // A: 128 rows * 8
        int idx = tid + 128 * t;
        int row = idx >> 3, c8 = idx & 7;
        uint32_t so = (uint32_t)(row * 128 + ((c8 * 16) ^ ((row & 7) << 4)));
        cpasync16(sbase + so, g_x16 + (size_t)(m0 + row) * KSTR + koff + c8 * 8);
    }
#pragma unroll
    for (int t = 0; t < 8; ++t) {                       // B: 128 rows * 8
        int idx = tid + 128 * t;
        int row = idx >> 3, c8 = idx & 7;
        uint32_t so = (uint32_t)(row * 128 + ((c8 * 16) ^ ((row & 7) << 4)));
        cpasync16(sbase + G_PA + so, g_W16 + (size_t)(n0 + row) * KSTR + koff + c8 * 8);
    }
    cp_commit();
}

__global__ void __launch_bounds__(128, 2) gemm_kernel(
    const float* __restrict__ bias, float* __restrict__ out)
{
    extern __shared__ char smc[];
    const uint32_t sb = smem_to_u32(smc);
    const int tid = threadIdx.x;
    const int lane = tid & 31;
    const int wid = tid >> 5;
    const int wm = wid >> 1;        // 0..1 -> m offset *64
    const int wn = wid & 1;         // 0..1 -> n offset *64
    const int n0 = blockIdx.x * 128;
    const int m0 = blockIdx.y * 128;

    const int jg = lane >> 3, rr = lane & 7;
    const uint32_t xorv = (uint32_t)(rr << 4);
    const uint32_t arow = (uint32_t)((jg & 1) * 8 + rr);
    const uint32_t akb  = (uint32_t)((jg >> 1) * 16);
    const uint32_t brow = (uint32_t)((jg >> 1) * 8 + rr);
    const uint32_t bkb  = (uint32_t)((jg & 1) * 16);

    float acc[4][8][4];
#pragma unroll
    for (int i = 0; i < 4; ++i)
#pragma unroll
        for (int j = 0; j < 8; ++j)
#pragma unroll
            for (int q = 0; q < 4; ++q) acc[i][j][q] = 0.0f;

    m_issue(sb, 0, 0, m0, n0, tid);
    m_issue(sb, 1, 1, m0, n0, tid);

#pragma unroll 1
    for (int c = 0; c < G_NCH; ++c) {
        const int s = c % 3;
        if (c < G_NCH - 1) asm volatile("cp.async.wait_group 1;" ::: "memory");
        else               asm volatile("cp.async.wait_group 0;" ::: "memory");
        __syncthreads();
        if (c + 2 < G_NCH) m_issue(sb, (c + 2) % 3, c + 2, m0, n0, tid);

        const uint32_t sA = sb + s * G_STG;
        const uint32_t sB = sA + G_PA;
#pragma unroll
        for (int k16 = 0; k16 < 4; ++k16) {
            const uint32_t kA = ((uint32_t)(k16 * 32) + akb) ^ xorv;
            const uint32_t kB = ((uint32_t)(k16 * 32) + bkb) ^ xorv;
            uint32_t ah[4][4], bh[4][4];
#pragma unroll
            for (int i = 0; i < 4; ++i) {
                uint32_t ro = (uint32_t)((wm * 64 + i * 16 + arow) * 128);
                ldsm4(ah[i], sA + ro + kA);
            }
#pragma unroll
            for (int j2 = 0; j2 < 4; ++j2) {
                uint32_t ro = (uint32_t)((wn * 64 + j2 * 16 + brow) * 128);
                ldsm4(bh[j2], sB + ro + kB);
            }
#pragma unroll
            for (int i = 0; i < 4; ++i)
#pragma unroll
                for (int j2 = 0; j2 < 4; ++j2) {
                    mma16816(acc[i][j2 * 2],     ah[i], bh[j2]);
                    mma16816(acc[i][j2 * 2 + 1], ah[i], bh[j2] + 2);
                }
        }
    }

    // Epilogue: bias + fp32 store
    const int gi = lane >> 2;
    const int tg = lane & 3;
#pragma unroll
    for (int j = 0; j < 8; ++j) {
        const int ncol = n0 + wn * 64 + j * 8 + tg * 2;
        const float b0 = bias[ncol], b1 = bias[ncol + 1];
#pragma unroll
        for (int i = 0; i < 4; ++i) {
            const int r0 = m0 + wm * 64 + i * 16 + gi;
            float2 v0 = make_float2(acc[i][j][0] + b0, acc[i][j][1] + b1);
            float2 v1 = make_float2(acc[i][j][2] + b0, acc[i][j][3] + b1);
            *(float2*)(out + (size_t)r0 * D_OUT + ncol) = v0;
            *(float2*)(out + (size_t)(r0 + 8) * D_OUT + ncol) = v1;
        }
    }
}

// ============================================================================
// Launch
// ============================================================================
extern "C" void kernel_launch(void* const* d_in, const int* in_sizes, int n_in,
                              void* d_out, int out_size)
{
    const float* x      = (const float*)d_in[0];
    const float* W      = (const float*)d_in[1];
    const float* bias   = (const float*)d_in[2];
    const float* routeW = (const float*)d_in[3];
    const float* loraA  = (const float*)d_in[4];
    const float* loraB  = (const float*)d_in[5];
    float* out = (float*)d_out;

    const size_t RES = (size_t)T_TOK * D_OUT;
    float* out_rw;
    float* out_gs;
    if ((size_t)out_size >= RES + 2u * T_TOK * N_EXP) {
        out_rw = out + RES;
        out_gs = out_rw + (size_t)T_TOK * N_EXP;
    } else {
        float* dummy;
        cudaGetSymbolAddress((void**)&dummy, g_dummy_rw);
        out_rw = dummy;
        out_gs = dummy + (size_t)T_TOK * N_EXP;
    }

    cudaFuncSetAttribute(prep_kernel,  cudaFuncAttributeMaxDynamicSharedMemorySize, GT_SMEM);
    cudaFuncSetAttribute(hgemm_kernel, cudaFuncAttributeMaxDynamicSharedMemorySize, H_SMEM);
    cudaFuncSetAttribute(gemm_kernel,  cudaFuncAttributeMaxDynamicSharedMemorySize, G_SMEM);

    prep_kernel<<<PREP_GRID, 256, GT_SMEM>>>(x, routeW, W, loraA, loraB, out_rw, out_gs);
    hgemm_kernel<<<dim3(T_TOK / 64, 2), 256, H_SMEM>>>();
    combine_kernel<<<(T_TOK * 32) / 256, 256>>>();
    gemm_kernel<<<dim3(D_OUT / 128, T_TOK / 128), 128, G_SMEM>>>(bias, out);   // #4 -> ncu
}

// round 17
// speedup vs baseline: 1.0844x; 1.0844x over previous
#include <cuda_runtime.h>
#include <cuda_bf16.h>
#include <cuda_fp16.h>
#include <cstdint>

// ============================================================================
// Problem constants
// ============================================================================
#define T_TOK   8192        // B*S
#define D_IN    4096
#define D_OUT   4096
#define N_EXP   8
#define RANK    16
#define KEXTRA  128         // E*R
#define KSTR    4224        // D_IN + KEXTRA (extended K)
#define SCALING 2.0f

// ============================================================================
// Persistent device scratch (static arrays: allocation-free)
// ============================================================================
__device__ __half g_x16[(size_t)T_TOK * KSTR];    // 69.2 MB
__device__ __half g_W16[(size_t)D_OUT * KSTR];    // 34.6 MB
__device__ __half g_A16[(size_t)KEXTRA * D_IN];   // 1 MB
__device__ float  g_hp[2][(size_t)T_TOK * KEXTRA]; // split-K partials, 8 MB
__device__ float  g_rw[(size_t)T_TOK * N_EXP];
__device__ float  g_dummy_rw[2 * T_TOK * N_EXP];

// ============================================================================
// Helpers (sm_80-compatible PTX only; ptxas targets plain sm_103)
// ============================================================================
__device__ __forceinline__ uint32_t smem_to_u32(const void* p) {
    uint32_t a;
    asm("{ .reg .u64 t; cvta.to.shared.u64 t, %1; cvt.u32.u64 %0, t; }" : "=r"(a) : "l"(p));
    return a;
}
__device__ __forceinline__ void cpasync16(uint32_t saddr, const void* g) {
    asm volatile("cp.async.cg.shared.global [%0], [%1], 16;" :: "r"(saddr), "l"(g));
}
__device__ __forceinline__ void cp_commit() {
    asm volatile("cp.async.commit_group;" ::: "memory");
}
__device__ __forceinline__ void ldsm4(uint32_t* r, uint32_t addr) {
    asm volatile("ldmatrix.sync.aligned.m8n8.x4.shared.b16 {%0,%1,%2,%3}, [%4];"
                 : "=r"(r[0]), "=r"(r[1]), "=r"(r[2]), "=r"(r[3]) : "r"(addr));
}
__device__ __forceinline__ void mma16816(float* c, const uint32_t* a, const uint32_t* b) {
    asm volatile(
        "mma.sync.aligned.m16n8k16.row.col.f32.f16.f16.f32 "
        "{%0,%1,%2,%3}, {%4,%5,%6,%7}, {%8,%9}, {%0,%1,%2,%3};"
        : "+f"(c[0]), "+f"(c[1]), "+f"(c[2]), "+f"(c[3])
        : "r"(a[0]), "r"(a[1]), "r"(a[2]), "r"(a[3]), "r"(b[0]), "r"(b[1]));
}

// ============================================================================
// Kernel: gate (fp32) + fused x->fp16 conversion. (R15 measured-best, verbatim)
// ============================================================================
#define GT_XROW 68
#define GT_XBUF (64 * GT_XROW)
#define GT_WBUF (8 * GT_XROW)
#define GT_XB0  0
#define GT_WS0  (2 * GT_XBUF)
#define GT_GS0  (GT_WS0 + 2 * GT_WBUF)
#define GT_FLOATS (GT_GS0 + 64 * 9)
#define GT_SMEM (GT_FLOATS * 4)            // 41472

__device__ __forceinline__ void gate_issue(uint32_t sb, int s, int kb,
                                           int tok0, int tid,
                                           const float* __restrict__ x,
                                           const float* __restrict__ routeW) {
#pragma unroll
    for (int t = 0; t < 4; ++t) {          // x chunk: 64 rows x 64 floats
        int idx = tid + 256 * t;
        int row = idx >> 4, c16 = idx & 15;
        uint32_t so = sb + (uint32_t)((GT_XB0 + s * GT_XBUF + row * GT_XROW + c16 * 4) * 4);
        cpasync16(so, x + (size_t)(tok0 + row) * D_IN + kb * 64 + c16 * 4);
    }
    if (tid < 128) {                       // routeW chunk: 8 rows x 64 floats
        int row = tid >> 4, c16 = tid & 15;
        uint32_t so = sb + (uint32_t)((GT_WS0 + s * GT_WBUF + row * GT_XROW + c16 * 4) * 4);
        cpasync16(so, routeW + (size_t)row * D_IN + kb * 64 + c16 * 4);
    }
    cp_commit();
}

__global__ void __launch_bounds__(256) gate_kernel(
    const float* __restrict__ x, const float* __restrict__ routeW,
    float* __restrict__ out_rw, float* __restrict__ out_gs)
{
    extern __shared__ float sm[];
    const uint32_t sb = smem_to_u32(sm);
    float* gs = sm + GT_GS0;

    const int tid = threadIdx.x;
    const int tok0 = blockIdx.x * 64;
    const int t  = tid >> 2;
    const int eq = tid & 3;

    gate_issue(sb, 0, 0, tok0, tid, x, routeW);
    gate_issue(sb, 1, 1, tok0, tid, x, routeW);

    float a0 = 0.0f, a1 = 0.0f;
#pragma unroll 1
    for (int kb = 0; kb < D_IN / 64; ++kb) {
        const int s = kb & 1;
        if (kb < D_IN / 64 - 1) asm volatile("cp.async.wait_group 1;" ::: "memory");
        else                    asm volatile("cp.async.wait_group 0;" ::: "memory");
        __syncthreads();

        const float* xb = sm + GT_XB0 + s * GT_XBUF + t * GT_XROW;
        const float* w0 = sm + GT_WS0 + s * GT_WBUF + eq * GT_XROW;
        const float* w1 = w0 + 4 * GT_XROW;
#pragma unroll
        for (int k4 = 0; k4 < 16; ++k4) {
            float4 xv = *(const float4*)(xb + k4 * 4);
            float4 wa = *(const float4*)(w0 + k4 * 4);
            float4 wb = *(const float4*)(w1 + k4 * 4);
            a0 = fmaf(xv.x, wa.x, a0); a0 = fmaf(xv.y, wa.y, a0);
            a0 = fmaf(xv.z, wa.z, a0); a0 = fmaf(xv.w, wa.w, a0);
            a1 = fmaf(xv.x, wb.x, a1); a1 = fmaf(xv.y, wb.y, a1);
            a1 = fmaf(xv.z, wb.z, a1); a1 = fmaf(xv.w, wb.w, a1);
        }
        {
            const float* xr = sm + GT_XB0 + s * GT_XBUF + t * GT_XROW + eq * 16;
            __half* dst = g_x16 + (size_t)(tok0 + t) * KSTR + kb * 64 + eq * 16;
#pragma unroll
            for (int j = 0; j < 4; ++j) {
                float4 v = *(const float4*)(xr + j * 4);
                __half2 p0 = __floats2half2_rn(v.x, v.y);
                __half2 p1 = __floats2half2_rn(v.z, v.w);
                uint2 o;
                o.x = *(uint32_t*)&p0;
                o.y = *(uint32_t*)&p1;
                *(uint2*)(dst + j * 4) = o;
            }
        }
        __syncthreads();
        if (kb + 2 < D_IN / 64) gate_issue(sb, s, kb + 2, tok0, tid, x, routeW);
    }

    gs[t * 9 + eq] = a0;
    gs[t * 9 + eq + 4] = a1;
    __syncthreads();

    if (tid < 64) {
        float g[N_EXP], m = -1e30f;
#pragma unroll
        for (int j = 0; j < N_EXP; ++j) { g[j] = gs[tid * 9 + j]; m = fmaxf(m, g[j]); }
        float p[N_EXP], s = 0.0f;
#pragma unroll
        for (int j = 0; j < N_EXP; ++j) { p[j] = expf(g[j] - m); s += p[j]; }
        float inv = 1.0f / s;
#pragma unroll
        for (int j = 0; j < N_EXP; ++j) p[j] *= inv;

        int i1 = 0;
#pragma unroll
        for (int j = 1; j < N_EXP; ++j) if (p[j] > p[i1]) i1 = j;
        int i2 = (i1 == 0) ? 1 : 0;
#pragma unroll
        for (int j = 0; j < N_EXP; ++j) if (j != i1 && p[j] > p[i2]) i2 = j;

        float denom = p[i1] + p[i2] + 1e-9f;
        float w1 = p[i1] / denom, w2 = p[i2] / denom;

        size_t ob = (size_t)(tok0 + tid) * N_EXP;
#pragma unroll
        for (int j = 0; j < N_EXP; ++j) {
            out_gs[ob + j] = g[j];
            float w = (j == i1) ? w1 : ((j == i2) ? w2 : 0.0f);
            out_rw[ob + j] = w;
            g_rw[ob + j] = w;
        }
    }
}

// ============================================================================
// Kernel: convAll — W->fp16, lora_A->fp16, lora_B pack. (R15 verbatim)
// ============================================================================
__device__ __forceinline__ void conv_store(const float* src, __half* dst,
                                           size_t ridx, int c4,
                                           int src_stride, int dst_stride) {
    float4 v = *(const float4*)(src + ridx * src_stride + c4 * 4);
    __half2 h0 = __floats2half2_rn(v.x, v.y);
    __half2 h1 = __floats2half2_rn(v.z, v.w);
    uint2 o;
    o.x = *(uint32_t*)&h0;
    o.y = *(uint32_t*)&h1;
    *(uint2*)(dst + ridx * dst_stride + c4 * 4) = o;
}
__global__ void convAll_kernel(const float* __restrict__ W,
                               const float* __restrict__ loraA,
                               const float* __restrict__ loraB) {
    int b = blockIdx.x;
    if (b < 16384) {
        size_t idx = (size_t)b * 256 + threadIdx.x;            // D_OUT*1024
        conv_store(W, g_W16, idx >> 10, (int)(idx & 1023), D_IN, KSTR);
    } else if (b < 16896) {
        size_t idx = (size_t)(b - 16384) * 256 + threadIdx.x;  // KEXTRA*1024
        conv_store(loraA, g_A16, idx >> 10, (int)(idx & 1023), D_IN, D_IN);
    } else {
        int idx = (b - 16896) * 256 + threadIdx.x;             // D_OUT*KEXTRA
        int o = idx >> 7, kk = idx & 127;
        int e = kk >> 4, r = kk & 15;
        g_W16[(size_t)o * KSTR + D_IN + kk] =
            __float2half_rn(loraB[((size_t)e * D_OUT + o) * RANK + r]);
    }
}

// ============================================================================
// Kernel: hgemm — h = x * lora_A^T, SPLIT-K x2, 64-row tiles, 3-stage,
// OCCUPANCY 2: 256 CTAs fit in one wave (296 slots); busy SMs hold 16 warps
// -> latency hiding on a kernel measured at 31% tensor / 12.5% occ.
// ============================================================================
#define H_PA 8192
#define H_PB 16384
#define H_STG (H_PA + H_PB)            // 24576
#define H_SMEM (3 * H_STG)             // 73728 (occ 2: 147456 <= 228KB)
#define H_CHUNKS 32                    // per k-half

__device__ __forceinline__ void h_issue(uint32_t sb, int s, int c, int m0, int tid) {
    uint32_t sbase = sb + s * H_STG;
    size_t koff = (size_t)c * 64;
#pragma unroll
    for (int t = 0; t < 2; ++t) {                       // A: 64 rows * 8
        int idx = tid + 256 * t;
        int row = idx >> 3, c8 = idx & 7;
        uint32_t so = (uint32_t)(row * 128 + ((c8 * 16) ^ ((row & 7) << 4)));
        cpasync16(sbase + so, g_x16 + (size_t)(m0 + row) * KSTR + koff + c8 * 8);
    }
#pragma unroll
    for (int t = 0; t < 4; ++t) {                       // B: 128 rows * 8
        int idx = tid + 256 * t;
        int row = idx >> 3, c8 = idx & 7;
        uint32_t so = (uint32_t)(row * 128 + ((c8 * 16) ^ ((row & 7) << 4)));
        cpasync16(sbase + H_PA + so, g_A16 + (size_t)row * D_IN + koff + c8 * 8);
    }
    cp_commit();
}

__global__ void __launch_bounds__(256, 2) hgemm_kernel() {
    extern __shared__ char smc[];
    const uint32_t sb = smem_to_u32(smc);
    const int tid = threadIdx.x;
    const int lane = tid & 31;
    const int wid = tid >> 5;
    const int wm = wid >> 2;        // 0..1
    const int wn = wid & 3;         // 0..3
    const int m0 = blockIdx.x * 64;
    const int ks = blockIdx.y;      // 0..1 k-half
    const int cbase = ks * H_CHUNKS;

    const int jg = lane >> 3, rr = lane & 7;
    const uint32_t xorv = (uint32_t)(rr << 4);
    const uint32_t arow = (uint32_t)((jg & 1) * 8 + rr);
    const uint32_t akb  = (uint32_t)((jg >> 1) * 16);
    const uint32_t brow = (uint32_t)((jg >> 1) * 8 + rr);
    const uint32_t bkb  = (uint32_t)((jg & 1) * 16);

    float acc[2][4][4];
#pragma unroll
    for (int i = 0; i < 2; ++i)
#pragma unroll
        for (int j = 0; j < 4; ++j)
#pragma unroll
            for (int q = 0; q < 4; ++q) acc[i][j][q] = 0.0f;

    h_issue(sb, 0, cbase + 0, m0, tid);
    h_issue(sb, 1, cbase + 1, m0, tid);

#pragma unroll 1
    for (int c = 0; c < H_CHUNKS; ++c) {
        const int s = c % 3;
        if (c < H_CHUNKS - 1) asm volatile("cp.async.wait_group 1;" ::: "memory");
        else                  asm volatile("cp.async.wait_group 0;" ::: "memory");
        __syncthreads();
        if (c + 2 < H_CHUNKS) h_issue(sb, (c + 2) % 3, cbase + c + 2, m0, tid);

        const uint32_t sA = sb + s * H_STG;
        const uint32_t sB = sA + H_PA;
#pragma unroll
        for (int k16 = 0; k16 < 4; ++k16) {
            const uint32_t kA = ((uint32_t)(k16 * 32) + akb) ^ xorv;
            const uint32_t kB = ((uint32_t)(k16 * 32) + bkb) ^ xorv;
            uint32_t ah[2][4];
#pragma unroll
            for (int i = 0; i < 2; ++i) {
                uint32_t ro = (uint32_t)((wm * 32 + i * 16 + arow) * 128);
                ldsm4(ah[i], sA + ro + kA);
            }
#pragma unroll
            for (int j2 = 0; j2 < 2; ++j2) {
                uint32_t bh[4];
                uint32_t ro = (uint32_t)((wn * 32 + j2 * 16 + brow) * 128);
                ldsm4(bh, sB + ro + kB);
#pragma unroll
                for (int i = 0; i < 2; ++i) {
                    mma16816(acc[i][j2 * 2],     ah[i], bh);
                    mma16816(acc[i][j2 * 2 + 1], ah[i], bh + 2);
                }
            }
        }
    }

    // Epilogue: store fp32 partials
    float* hp = g_hp[ks];
    const int gi = lane >> 2;
    const int tg = lane & 3;
#pragma unroll
    for (int i = 0; i < 2; ++i)
#pragma unroll
        for (int j = 0; j < 4; ++j) {
            int col = wn * 32 + j * 8 + tg * 2;
#pragma unroll
            for (int half = 0; half < 2; ++half) {
                int r = m0 + wm * 32 + i * 16 + gi + half * 8;
                float2 v = make_float2(acc[i][j][half * 2 + 0], acc[i][j][half * 2 + 1]);
                *(float2*)(hp + (size_t)r * KEXTRA + col) = v;
            }
        }
}

// ============================================================================
// Kernel: combine — g = SCALING * rw * (hp0 + hp1) -> fp16 lora cols of g_x16
// ============================================================================
__global__ void __launch_bounds__(256) combine_kernel() {
    int idx = blockIdx.x * 256 + threadIdx.x;   // T_TOK*32 threads, 4 cols each
    int t = idx >> 5;
    int c = (idx & 31) * 4;
    float rw = SCALING * g_rw[(size_t)t * N_EXP + (c >> 4)];
    const float* p0 = g_hp[0] + (size_t)t * KEXTRA + c;
    const float* p1 = g_hp[1] + (size_t)t * KEXTRA + c;
    float4 a = *(const float4*)p0;
    float4 b = *(const float4*)p1;
    __half2 h0 = __floats2half2_rn((a.x + b.x) * rw, (a.y + b.y) * rw);
    __half2 h1 = __floats2half2_rn((a.z + b.z) * rw, (a.w + b.w) * rw);
    uint2 o;
    o.x = *(uint32_t*)&h0;
    o.y = *(uint32_t*)&h1;
    *(uint2*)(g_x16 + (size_t)t * KSTR + D_IN + c) = o;
}

// ============================================================================
// Kernel: main GEMM — FROZEN (R15 measured plateau: tensor ~75%).
// 128x128xKC64, 4 warps (2x2) of 64x64 tiles, 128 threads, occ 2, 3-stage.
// ============================================================================
#define G_PA 16384
#define G_PB 16384
#define G_STG (G_PA + G_PB)            // 32768
#define G_SMEM (3 * G_STG)             // 98304
#define G_NCH (KSTR / 64)              // 66

__device__ __forceinline__ void m_issue(uint32_t sb, int s, int c, int m0, int n0, int tid) {
    uint32_t sbase = sb + s * G_STG;
    size_t koff = (size_t)c * 64;
#pragma unroll
    for (int t = 0; t < 8; ++t) {                       // A: 128 rows * 8
        int idx = tid + 128 * t;
        int row = idx >> 3, c8 = idx & 7;
        uint32_t so = (uint32_t)(row * 128 + ((c8 * 16) ^ ((row & 7) << 4)));
        cpasync16(sbase + so, g_x16 + (size_t)(m0 + row) * KSTR + koff + c8 * 8);
    }
#pragma unroll
    for (int t = 0; t < 8; ++t) {                       // B: 128 rows * 8
        int idx = tid + 128 * t;
        int row = idx >> 3, c8 = idx & 7;
        uint32_t so = (uint32_t)(row * 128 + ((c8 * 16) ^ ((row & 7) << 4)));
        cpasync16(sbase + G_PA + so, g_W16 + (size_t)(n0 + row) * KSTR + koff + c8 * 8);
    }
    cp_commit();
}

__global__ void __launch_bounds__(128, 2) gemm_kernel(
    const float* __restrict__ bias, float* __restrict__ out)
{
    extern __shared__ char smc[];
    const uint32_t sb = smem_to_u32(smc);
    const int tid = threadIdx.x;
    const int lane = tid & 31;
    const int wid = tid >> 5;
    const int wm = wid >> 1;        // 0..1 -> m offset *64
    const int wn = wid & 1;         // 0..1 -> n offset *64
    const int n0 = blockIdx.x * 128;
    const int m0 = blockIdx.y * 128;

    const int jg = lane >> 3, rr = lane & 7;
    const uint32_t xorv = (uint32_t)(rr << 4);
    const uint32_t arow = (uint32_t)((jg & 1) * 8 + rr);
    const uint32_t akb  = (uint32_t)((jg >> 1) * 16);
    const uint32_t brow = (uint32_t)((jg >> 1) * 8 + rr);
    const uint32_t bkb  = (uint32_t)((jg & 1) * 16);

    float acc[4][8][4];
#pragma unroll
    for (int i = 0; i < 4; ++i)
#pragma unroll
        for (int j = 0; j < 8; ++j)
#pragma unroll
            for (int q = 0; q < 4; ++q) acc[i][j][q] = 0.0f;

    m_issue(sb, 0, 0, m0, n0, tid);
    m_issue(sb, 1, 1, m0, n0, tid);

#pragma unroll 1
    for (int c = 0; c < G_NCH; ++c) {
        const int s = c % 3;
        if (c < G_NCH - 1) asm volatile("cp.async.wait_group 1;" ::: "memory");
        else               asm volatile("cp.async.wait_group 0;" ::: "memory");
        __syncthreads();
        if (c + 2 < G_NCH) m_issue(sb, (c + 2) % 3, c + 2, m0, n0, tid);

        const uint32_t sA = sb + s * G_STG;
        const uint32_t sB = sA + G_PA;
#pragma unroll
        for (int k16 = 0; k16 < 4; ++k16) {
            const uint32_t kA = ((uint32_t)(k16 * 32) + akb) ^ xorv;
            const uint32_t kB = ((uint32_t)(k16 * 32) + bkb) ^ xorv;
            uint32_t ah[4][4], bh[4][4];
#pragma unroll
            for (int i = 0; i < 4; ++i) {
                uint32_t ro = (uint32_t)((wm * 64 + i * 16 + arow) * 128);
                ldsm4(ah[i], sA + ro + kA);
            }
#pragma unroll
            for (int j2 = 0; j2 < 4; ++j2) {
                uint32_t ro = (uint32_t)((wn * 64 + j2 * 16 + brow) * 128);
                ldsm4(bh[j2], sB + ro + kB);
            }
#pragma unroll
            for (int i = 0; i < 4; ++i)
#pragma unroll
                for (int j2 = 0; j2 < 4; ++j2) {
                    mma16816(acc[i][j2 * 2],     ah[i], bh[j2]);
                    mma16816(acc[i][j2 * 2 + 1], ah[i], bh[j2] + 2);
                }
        }
    }

    // Epilogue: bias + fp32 store
    const int gi = lane >> 2;
    const int tg = lane & 3;
#pragma unroll
    for (int j = 0; j < 8; ++j) {
        const int ncol = n0 + wn * 64 + j * 8 + tg * 2;
        const float b0 = bias[ncol], b1 = bias[ncol + 1];
#pragma unroll
        for (int i = 0; i < 4; ++i) {
            const int r0 = m0 + wm * 64 + i * 16 + gi;
            float2 v0 = make_float2(acc[i][j][0] + b0, acc[i][j][1] + b1);
            float2 v1 = make_float2(acc[i][j][2] + b0, acc[i][j][3] + b1);
            *(float2*)(out + (size_t)r0 * D_OUT + ncol) = v0;
            *(float2*)(out + (size_t)(r0 + 8) * D_OUT + ncol) = v1;
        }
    }
}

// ============================================================================
// Launch
// ============================================================================
extern "C" void kernel_launch(void* const* d_in, const int* in_sizes, int n_in,
                              void* d_out, int out_size)
{
    const float* x      = (const float*)d_in[0];
    const float* W      = (const float*)d_in[1];
    const float* bias   = (const float*)d_in[2];
    const float* routeW = (const float*)d_in[3];
    const float* loraA  = (const float*)d_in[4];
    const float* loraB  = (const float*)d_in[5];
    float* out = (float*)d_out;

    const size_t RES = (size_t)T_TOK * D_OUT;
    float* out_rw;
    float* out_gs;
    if ((size_t)out_size >= RES + 2u * T_TOK * N_EXP) {
        out_rw = out + RES;
        out_gs = out_rw + (size_t)T_TOK * N_EXP;
    } else {
        float* dummy;
        cudaGetSymbolAddress((void**)&dummy, g_dummy_rw);
        out_rw = dummy;
        out_gs = dummy + (size_t)T_TOK * N_EXP;
    }

    cudaFuncSetAttribute(gate_kernel,  cudaFuncAttributeMaxDynamicSharedMemorySize, GT_SMEM);
    cudaFuncSetAttribute(hgemm_kernel, cudaFuncAttributeMaxDynamicSharedMemorySize, H_SMEM);
    cudaFuncSetAttribute(gemm_kernel,  cudaFuncAttributeMaxDynamicSharedMemorySize, G_SMEM);

    gate_kernel<<<T_TOK / 64, 256, GT_SMEM>>>(x, routeW, out_rw, out_gs);
    convAll_kernel<<<16896 + (D_OUT * KEXTRA) / 256, 256>>>(W, loraA, loraB);
    hgemm_kernel<<<dim3(T_TOK / 64, 2), 256, H_SMEM>>>();
    combine_kernel<<<(T_TOK * 32) / 256, 256>>>();
    gemm_kernel<<<dim3(D_OUT / 128, T_TOK / 128), 128, G_SMEM>>>(bias, out);
}